// round 16
// baseline (speedup 1.0000x reference)
#include <cuda_runtime.h>
#include <cuda_bf16.h>
#include <cstdint>
#include <cstddef>

#define HID     1536
#define NH      12
#define HD      128
#define MLP     6144
#define LX      4352
#define NC      20
#define L2V     4116
#define L2P     4352
#define QKVW    4608
#define CATW    7680
#define NSPLIT  4
#define SOFT_SCALE 0.08838834764831845f

typedef unsigned int u32;
typedef unsigned long long u64;

#if defined(__CUDA_ARCH_FEAT_SM103_ALL) || defined(__CUDA_ARCH_FEAT_SM100_ALL) || defined(__CUDA_ARCH_FEAT_SM101_ALL)
#define HAS_TCGEN05 1
#else
#define HAS_TCGEN05 0
#endif

// ---------------- scratch ----------------
__device__ __align__(256) float g_m[3 * HID];
__device__ __align__(256) float g_xm[(size_t)LX * HID];
__device__ __align__(256) float g_xm2[(size_t)L2P * HID];
__device__ __align__(256) float g_h[(size_t)LX * QKVW];
__device__ __align__(256) float g_h2kv[(size_t)L2P * 3072];
__device__ __align__(256) float g_h2f[(size_t)128 * HID];
__device__ __align__(256) float g_q[(size_t)NH * LX * HD];
__device__ __align__(256) float g_k[(size_t)NH * LX * HD];
__device__ __align__(256) float g_v[(size_t)NH * HD * LX];
__device__ __align__(256) float g_q2[(size_t)NH * 128 * HD];
__device__ __align__(256) float g_k2[(size_t)NH * L2P * HD];
__device__ __align__(256) float g_v2[(size_t)NH * HD * L2P];
__device__ __align__(256) float g_cat[(size_t)LX * CATW];
__device__ __align__(256) float g_cat2[(size_t)128 * CATW];
__device__ __align__(256) float g_O2p[(size_t)NSPLIT * NH * 128 * HD];
__device__ __align__(256) float g_l2[(size_t)NSPLIT * NH * 128];

// ---------------- PTX helpers ----------------
__device__ __forceinline__ u32 s2u(const void* p) { return (u32)__cvta_generic_to_shared(p); }
__device__ __forceinline__ u32 swz(u32 o) { return o ^ ((o >> 3) & 0x70); }
__device__ __forceinline__ void cp16(u32 dst, const void* src) {
    asm volatile("cp.async.cg.shared.global [%0], [%1], 16;" :: "r"(dst), "l"(src));
}
__device__ __forceinline__ void cp_commit() { asm volatile("cp.async.commit_group;" ::: "memory"); }
template <int N> __device__ __forceinline__ void cp_wait() {
    asm volatile("cp.async.wait_group %0;" :: "n"(N) : "memory");
}
__device__ __forceinline__ bool elect1() {
    u32 p;
    asm volatile("{\n\t.reg .pred p;\n\telect.sync _|p, 0xFFFFFFFF;\n\tselp.b32 %0,1,0,p;\n\t}" : "=r"(p));
    return p != 0;
}
__device__ __forceinline__ u64 sdesc(u32 addr) {
    return 0x4000404000010000ull | (u64)((addr >> 4) & 0x3FFF);
}
__device__ __forceinline__ void mbar_init_cnt(u32 a, u32 cnt) {
    asm volatile("mbarrier.init.shared.b64 [%0], %1;" :: "r"(a), "r"(cnt) : "memory");
}
__device__ __forceinline__ void mbar_init(u32 a) { mbar_init_cnt(a, 1); }
__device__ __forceinline__ void mbar_wait(u32 a, u32 parity) {
    asm volatile(
        "{\n\t.reg .pred P;\n"
        "LW_%=:\n\t"
        "mbarrier.try_wait.parity.acquire.cta.shared::cta.b64 P, [%0], %1, 0x989680;\n\t"
        "@P bra LD_%=;\n\t"
        "bra LW_%=;\n"
        "LD_%=:\n\t}" :: "r"(a), "r"(parity) : "memory");
}
__device__ __forceinline__ void fence_async_shared() {
    asm volatile("fence.proxy.async.shared::cta;" ::: "memory");
}
__device__ __forceinline__ void fence_async_all() {
    asm volatile("fence.proxy.async;" ::: "memory");
}
__device__ __forceinline__ u32 ctarank() {
    u32 r; asm("mov.u32 %0, %%cluster_ctarank;" : "=r"(r)); return r;
}
__device__ __forceinline__ void cluster_sync() {
    asm volatile("barrier.cluster.arrive.aligned;" ::: "memory");
    asm volatile("barrier.cluster.wait.aligned;" ::: "memory");
}
__device__ __forceinline__ void mbar_arrive_rank0(u32 local_addr) {
    asm volatile(
        "{\n\t.reg .b32 ra;\n\t"
        "mapa.shared::cluster.u32 ra, %0, 0;\n\t"
        "mbarrier.arrive.shared::cluster.b64 _, [ra];\n\t}"
        :: "r"(local_addr) : "memory");
}
__device__ __forceinline__ void tc_commit(u32 mbar) {
#if HAS_TCGEN05
    asm volatile("tcgen05.commit.cta_group::1.mbarrier::arrive::one.shared::cluster.b64 [%0];"
                 :: "r"(mbar) : "memory");
#else
    (void)mbar;
#endif
}
__device__ __forceinline__ void tc_commit_mc2(u32 mbar) {
#if HAS_TCGEN05
    asm volatile(
        "tcgen05.commit.cta_group::2.mbarrier::arrive::one.shared::cluster.multicast::cluster.b64 [%0], %1;"
        :: "r"(mbar), "h"((unsigned short)3) : "memory");
#else
    (void)mbar;
#endif
}
__device__ __forceinline__ void mma_tf32(u32 d, u64 ad, u64 bd, u32 idesc, u32 en) {
#if HAS_TCGEN05
    asm volatile(
        "{\n\t.reg .pred p;\n\tsetp.ne.u32 p, %4, 0;\n\t"
        "tcgen05.mma.cta_group::1.kind::tf32 [%0], %1, %2, %3, {%5,%5,%5,%5}, p;\n\t}"
        :: "r"(d), "l"(ad), "l"(bd), "r"(idesc), "r"(en), "r"(0u) : "memory");
#else
    (void)d; (void)ad; (void)bd; (void)idesc; (void)en;
#endif
}
__device__ __forceinline__ void mma_tf32_cg2(u32 d, u64 ad, u64 bd, u32 idesc, u32 en) {
#if HAS_TCGEN05
    asm volatile(
        "{\n\t.reg .pred p;\n\tsetp.ne.u32 p, %4, 0;\n\t"
        "tcgen05.mma.cta_group::2.kind::tf32 [%0], %1, %2, %3, {%5,%5,%5,%5,%5,%5,%5,%5}, p;\n\t}"
        :: "r"(d), "l"(ad), "l"(bd), "r"(idesc), "r"(en), "r"(0u) : "memory");
#else
    (void)d; (void)ad; (void)bd; (void)idesc; (void)en;
#endif
}
__device__ __forceinline__ void tc_fence_after() {
#if HAS_TCGEN05
    asm volatile("tcgen05.fence::after_thread_sync;" ::: "memory");
#endif
}
__device__ __forceinline__ void tc_fence_before() {
#if HAS_TCGEN05
    asm volatile("tcgen05.fence::before_thread_sync;" ::: "memory");
#endif
}
__device__ __forceinline__ void tmem_alloc(u32 dst_smem, u32 ncols) {
#if HAS_TCGEN05
    asm volatile("tcgen05.alloc.cta_group::1.sync.aligned.shared::cta.b32 [%0], %1;"
                 :: "r"(dst_smem), "r"(ncols) : "memory");
#else
    (void)dst_smem; (void)ncols;
#endif
}
__device__ __forceinline__ void tmem_relinquish() {
#if HAS_TCGEN05
    asm volatile("tcgen05.relinquish_alloc_permit.cta_group::1.sync.aligned;");
#endif
}
__device__ __forceinline__ void tmem_dealloc(u32 tmem, u32 ncols) {
#if HAS_TCGEN05
    asm volatile("tcgen05.dealloc.cta_group::1.sync.aligned.b32 %0, %1;" :: "r"(tmem), "r"(ncols));
#else
    (void)tmem; (void)ncols;
#endif
}
__device__ __forceinline__ void tmem_alloc_cg2(u32 dst_smem, u32 ncols) {
#if HAS_TCGEN05
    asm volatile("tcgen05.alloc.cta_group::2.sync.aligned.shared::cta.b32 [%0], %1;"
                 :: "r"(dst_smem), "r"(ncols) : "memory");
#else
    (void)dst_smem; (void)ncols;
#endif
}
__device__ __forceinline__ void tmem_relinquish_cg2() {
#if HAS_TCGEN05
    asm volatile("tcgen05.relinquish_alloc_permit.cta_group::2.sync.aligned;");
#endif
}
__device__ __forceinline__ void tmem_dealloc_cg2(u32 tmem, u32 ncols) {
#if HAS_TCGEN05
    asm volatile("tcgen05.dealloc.cta_group::2.sync.aligned.b32 %0, %1;" :: "r"(tmem), "r"(ncols));
#else
    (void)tmem; (void)ncols;
#endif
}
__device__ __forceinline__ void tmem_wait_ld() {
#if HAS_TCGEN05
    asm volatile("tcgen05.wait::ld.sync.aligned;" ::: "memory");
#endif
}
__device__ __forceinline__ void ldtm32(u32* r, u32 a) {
#if HAS_TCGEN05
    asm volatile(
        "tcgen05.ld.sync.aligned.32x32b.x32.b32 "
        "{%0, %1, %2, %3, %4, %5, %6, %7, "
        " %8, %9, %10, %11, %12, %13, %14, %15, "
        " %16, %17, %18, %19, %20, %21, %22, %23, "
        " %24, %25, %26, %27, %28, %29, %30, %31}, [%32];"
        : "=r"(r[0]),  "=r"(r[1]),  "=r"(r[2]),  "=r"(r[3]),
          "=r"(r[4]),  "=r"(r[5]),  "=r"(r[6]),  "=r"(r[7]),
          "=r"(r[8]),  "=r"(r[9]),  "=r"(r[10]), "=r"(r[11]),
          "=r"(r[12]), "=r"(r[13]), "=r"(r[14]), "=r"(r[15]),
          "=r"(r[16]), "=r"(r[17]), "=r"(r[18]), "=r"(r[19]),
          "=r"(r[20]), "=r"(r[21]), "=r"(r[22]), "=r"(r[23]),
          "=r"(r[24]), "=r"(r[25]), "=r"(r[26]), "=r"(r[27]),
          "=r"(r[28]), "=r"(r[29]), "=r"(r[30]), "=r"(r[31])
        : "r"(a));
#else
#pragma unroll
    for (int i = 0; i < 32; ++i) r[i] = 0u;
    (void)a;
#endif
}
__device__ __forceinline__ float gelu_f(float x) {
    float u = 0.7978845608028654f * (x + 0.044715f * x * x * x);
    return 0.5f * x * (1.f + tanhf(u));
}

// ---------------------------------------------------------------------------
// cg2 GEMM: cluster pair computes 256(M) x 512(N), K-chunk 32.
// Per CTA/chunk: A own 128 rows (16KB) + B own halves (32KB). 4 stages.
// ---------------------------------------------------------------------------
#define CG_STAGES 4
#define CG_STRIDE 49152
#define SMEM_CG   (2048 + CG_STAGES * CG_STRIDE)
#define CG_IDESC  ((1u << 4) | (2u << 7) | (2u << 10) | (32u << 17) | (16u << 24))

// epi: 0 bias, 1 res+gate*(acc+bias), 2 gelu(acc+bias)
__device__ __forceinline__ void cg2_body(
    const float* __restrict__ A, const float* __restrict__ B, float* __restrict__ C,
    int K, int lda, int ldb, int ldc, int bm, int bn,
    const float* __restrict__ bias, const float* __restrict__ res, int ldres,
    const float* __restrict__ gate, int Mstore, int epi,
    u32 sb, int tid)
{
    const u32 done0  = sb + 64;    // 4 x 8B, local, multicast-armed
    const u32 ready0 = sb + 128;   // 4 x 8B, used on rank0, count=2
    const u32 tile0  = sb + 2048;
    const u32 rank = ctarank();
    const int amBase = bm + (int)rank * 128;

    if (tid == 0) {
        for (int s = 0; s < CG_STAGES; ++s) {
            mbar_init(done0 + 8 * s);
            mbar_init_cnt(ready0 + 8 * s, 2);
        }
    }
    if (tid < 32) { tmem_alloc_cg2(sb, 512); tmem_relinquish_cg2(); }
    __syncthreads();
    u32 tmem;
    asm volatile("ld.shared.b32 %0, [%1];" : "=r"(tmem) : "r"(sb));

    const int nk = K >> 5;

#define CG_LOAD(pp, st)                                                         \
    do {                                                                        \
        _Pragma("unroll")                                                       \
        for (int i = 0; i < 4; ++i) {     /* A half: 128 rows x 128B */         \
            int u = tid + (i << 8);                                             \
            int r_ = u >> 3, s_ = u & 7;                                        \
            cp16((st) + swz((u32)((r_ << 7) + (s_ << 4))),                      \
                 A + (size_t)(amBase + r_) * lda + ((pp) << 5) + (s_ << 2));    \
        }                                                                       \
        _Pragma("unroll")                                                       \
        for (int i = 0; i < 8; ++i) {     /* B halves: 2 x 128 rows x 128B */   \
            int u = tid + (i << 8);                                             \
            int sub = u >> 10, rem = u & 1023;                                  \
            int r_ = rem >> 3, s_ = rem & 7;                                    \
            cp16((st) + 16384u + (u32)sub * 16384u +                            \
                     swz((u32)((r_ << 7) + (s_ << 4))),                         \
                 B + (size_t)(bn + sub * 256 + (int)rank * 128 + r_) * ldb +    \
                     ((pp) << 5) + (s_ << 2));                                  \
        }                                                                       \
    } while (0)

    for (int p = 0; p < CG_STAGES - 1; ++p) {
        if (p < nk) CG_LOAD(p, tile0 + (u32)p * CG_STRIDE);
        cp_commit();
    }

    cluster_sync();   // mbar init + first loads visible before cross-CTA traffic

    for (int it = 0; it < nk; ++it) {
        const int b = it & 3;
        const u32 stg = tile0 + (u32)b * CG_STRIDE;

        cp_wait<CG_STAGES - 2>();
        fence_async_shared();
        fence_async_all();
        __syncthreads();
        if (tid == 0) mbar_arrive_rank0(ready0 + 8 * b);

        if (rank == 0 && tid < 32) {
            if (elect1()) {
                mbar_wait(ready0 + 8 * b, (u32)((it >> 2) & 1));
                u64 da = sdesc(stg);
#pragma unroll
                for (int nh = 0; nh < 2; ++nh) {
                    u64 db = sdesc(stg + 16384u + (u32)nh * 16384u);
#pragma unroll
                    for (int j = 0; j < 4; ++j)
                        mma_tf32_cg2(tmem + (u32)nh * 256, da + 2 * j, db + 2 * j,
                                     CG_IDESC, (u32)((it > 0) || (j > 0)));
                }
                tc_commit_mc2(done0 + 8 * b);
            }
        }

        const int p = it + CG_STAGES - 1;
        if (p < nk) {
            if (it >= 1)
                mbar_wait(done0 + 8 * ((it - 1) & 3), (u32)(((it - 1) >> 2) & 1));
            CG_LOAD(p, tile0 + (u32)(p & 3) * CG_STRIDE);
        }
        cp_commit();
    }
#undef CG_LOAD

    mbar_wait(done0 + 8 * ((nk - 1) & 3), (u32)(((nk - 1) >> 2) & 1));
    tc_fence_after();

    {
        const int w = tid >> 5, lane = tid & 31;
        const int ch = w >> 2;                       // column half: 0 or 1
        const int row = amBase + (w & 3) * 32 + lane;
        const bool doSt = row < Mstore;
        float* crow = C + (size_t)row * ldc;
        const float* rrow = (epi == 1 && doSt) ? (res + (size_t)row * ldres) : nullptr;
        const u32 tbase = tmem + (u32)ch * 256;
#pragma unroll
        for (int g = 0; g < 8; ++g) {
            u32 regs[32];
            ldtm32(regs, tbase + g * 32);
            tmem_wait_ld();
            if (doSt) {
#pragma unroll
                for (int q4 = 0; q4 < 8; ++q4) {
                    int col = bn + ch * 256 + g * 32 + q4 * 4;
                    float4 vv;
                    vv.x = __uint_as_float(regs[q4 * 4 + 0]);
                    vv.y = __uint_as_float(regs[q4 * 4 + 1]);
                    vv.z = __uint_as_float(regs[q4 * 4 + 2]);
                    vv.w = __uint_as_float(regs[q4 * 4 + 3]);
                    if (bias) {
                        float4 bb = *(const float4*)(bias + col);
                        vv.x += bb.x; vv.y += bb.y; vv.z += bb.z; vv.w += bb.w;
                    }
                    if (epi == 1) {
                        float4 rr = *(const float4*)(rrow + col);
                        float4 gg = *(const float4*)(gate + col);
                        vv.x = rr.x + gg.x * vv.x; vv.y = rr.y + gg.y * vv.y;
                        vv.z = rr.z + gg.z * vv.z; vv.w = rr.w + gg.w * vv.w;
                    } else if (epi == 2) {
                        vv.x = gelu_f(vv.x); vv.y = gelu_f(vv.y);
                        vv.z = gelu_f(vv.z); vv.w = gelu_f(vv.w);
                    }
                    *(float4*)(crow + col) = vv;
                }
            }
        }
    }
    __syncthreads();
    cluster_sync();                    // peer done reading our smem via MMA
    if (tid < 32) tmem_dealloc_cg2(tmem, 512);
    cluster_sync();
}

// Merged: qkv (9 N-tiles) | mlp-gelu (12) | kv2 (6); 17 M-tiles; pairs of CTAs.
__global__ __launch_bounds__(256, 1) __cluster_dims__(2, 1, 1)
void tc_cg2_merged(const float* __restrict__ xm, const float* __restrict__ xm2,
                   const float* __restrict__ w1,
                   float* __restrict__ h, float* __restrict__ catm,
                   float* __restrict__ h2kv, const float* __restrict__ b1)
{
    extern __shared__ char smem[];
    int t = blockIdx.x >> 1;
    const float* A; const float* B; float* C; const float* bs;
    int ldc, epi, mstore, ntil;
    if (t < 9 * 17) {
        A = xm;  B = w1;                      C = h;    bs = b1;
        ldc = QKVW; epi = 0; mstore = LX;  ntil = 9;
    } else if (t < 9 * 17 + 12 * 17) {
        t -= 9 * 17;
        A = xm;  B = w1 + (size_t)QKVW * HID; C = catm; bs = b1 + QKVW;
        ldc = CATW; epi = 2; mstore = LX;  ntil = 12;
    } else {
        t -= 9 * 17 + 12 * 17;
        A = xm2; B = w1 + (size_t)HID * HID;  C = h2kv; bs = b1 + HID;
        ldc = 3072; epi = 0; mstore = L2V; ntil = 6;
    }
    cg2_body(A, B, C, HID, HID, HID, ldc, (t / ntil) * 256, (t % ntil) * 512,
             bs, nullptr, 0, nullptr, mstore, epi, s2u(smem), threadIdx.x);
}

// out1: 3 N-tiles x 17 M-tiles, K=7680, EPI=1
__global__ __launch_bounds__(256, 1) __cluster_dims__(2, 1, 1)
void tc_cg2_out(const float* __restrict__ cat, const float* __restrict__ w2,
                float* __restrict__ out, const float* __restrict__ b2,
                const float* __restrict__ x, const float* __restrict__ gate)
{
    extern __shared__ char smem[];
    int t = blockIdx.x >> 1;
    cg2_body(cat, w2, out, CATW, CATW, CATW, HID, (t / 3) * 256, (t % 3) * 512,
             b2, x, HID, gate, LX, 1, s2u(smem), threadIdx.x);
}

// ---------------------------------------------------------------------------
// tc_gemm: original 128 x BN tile (block-2 M=128 GEMMs)
// ---------------------------------------------------------------------------
template <int BN>
__device__ __forceinline__ void load_chunk(u32 st, const float* A, const float* B,
                                           int bm, int bn, int kt, int lda, int ldb, int tid)
{
#pragma unroll
    for (int i = 0; i < 4; ++i) {
        int o = tid + (i << 8);
        int r = o >> 3, c = o & 7;
        cp16(st + swz((u32)((r << 7) + (c << 4))),
             A + (size_t)(bm + r) * lda + kt + (c << 2));
    }
    const u32 stB = st + 128 * 128;
#pragma unroll
    for (int i = 0; i < BN / 32; ++i) {
        int o = tid + (i << 8);
        int r = o >> 3, c = o & 7;
        cp16(stB + swz((u32)((r << 7) + (c << 4))),
             B + (size_t)(bn + r) * ldb + kt + (c << 2));
    }
}

template <int BN, int STAGES, int EPI>
__global__ __launch_bounds__(256, 1)
void tc_gemm(const float* __restrict__ A, const float* __restrict__ B, float* __restrict__ C,
             int K, int lda, int ldb, int ldc,
             size_t sA, size_t sB, size_t sC,
             const float* __restrict__ bias,
             const float* __restrict__ res, int ldres,
             const float* __restrict__ gate, int Mstore)
{
    constexpr int ASZ = 128 * 128;
    constexpr int STRIDE = ASZ + BN * 128;
    constexpr u32 IDESC = (1u << 4) | (2u << 7) | (2u << 10) |
                          ((u32)(BN / 8) << 17) | (8u << 24);

    extern __shared__ char smem[];
    const u32 sb = s2u(smem);
    const u32 mb0 = sb + 8;
    const u32 tile0 = sb + 1024;

    A += (size_t)blockIdx.z * sA;
    B += (size_t)blockIdx.z * sB;
    C += (size_t)blockIdx.z * sC;
    const int bm = blockIdx.y * 128;
    const int bn = blockIdx.x * BN;
    const int tid = threadIdx.x;

    if (tid == 0)
        for (int s = 0; s < STAGES; ++s) mbar_init(mb0 + 8 * s);
    if (tid < 32) { tmem_alloc(sb, BN); tmem_relinquish(); }
    __syncthreads();
    u32 tmem;
    asm volatile("ld.shared.b32 %0, [%1];" : "=r"(tmem) : "r"(sb));

    const int nk = K >> 5;
    for (int p = 0; p < STAGES - 1; ++p) {
        if (p < nk)
            load_chunk<BN>(tile0 + (p % STAGES) * STRIDE, A, B, bm, bn, p << 5, lda, ldb, tid);
        cp_commit();
    }

    for (int it = 0; it < nk; ++it) {
        const int b = it % STAGES;
        cp_wait<STAGES - 2>();
        fence_async_shared();
        __syncthreads();

        if (tid < 32) {
            u64 da = sdesc(tile0 + b * STRIDE);
            u64 db = sdesc(tile0 + b * STRIDE + ASZ);
            if (elect1()) {
#pragma unroll
                for (int j = 0; j < 4; ++j)
                    mma_tf32(tmem, da + j * 2, db + j * 2, IDESC, (u32)((it > 0) || (j > 0)));
                tc_commit(mb0 + 8 * b);
            }
        }
        const int p = it + STAGES - 1;
        if (p < nk) {
            if (it >= 1)
                mbar_wait(mb0 + 8 * (p % STAGES), (u32)(((it - 1) / STAGES) & 1));
            load_chunk<BN>(tile0 + (p % STAGES) * STRIDE, A, B, bm, bn, p << 5, lda, ldb, tid);
        }
        cp_commit();
    }

    mbar_wait(mb0 + 8 * ((nk - 1) % STAGES), (u32)(((nk - 1) / STAGES) & 1));
    tc_fence_after();

    if (tid < 128) {
        const int w = tid >> 5, lane = tid & 31;
        const int row = bm + w * 32 + lane;
        const bool doSt = row < Mstore;
        float* crow = C + (size_t)row * ldc;
        const float* rrow = (EPI == 1 && doSt) ? (res + (size_t)row * ldres) : nullptr;
#pragma unroll
        for (int g = 0; g < BN / 32; ++g) {
            u32 regs[32];
            ldtm32(regs, tmem + g * 32);
            tmem_wait_ld();
            if (doSt) {
#pragma unroll
                for (int q4 = 0; q4 < 8; ++q4) {
                    int col = bn + g * 32 + q4 * 4;
                    float4 vv;
                    vv.x = __uint_as_float(regs[q4 * 4 + 0]);
                    vv.y = __uint_as_float(regs[q4 * 4 + 1]);
                    vv.z = __uint_as_float(regs[q4 * 4 + 2]);
                    vv.w = __uint_as_float(regs[q4 * 4 + 3]);
                    if (bias) {
                        float4 bb = *(const float4*)(bias + col);
                        vv.x += bb.x; vv.y += bb.y; vv.z += bb.z; vv.w += bb.w;
                    }
                    if (EPI == 1) {
                        float4 rr = *(const float4*)(rrow + col);
                        float4 gg = *(const float4*)(gate + col);
                        vv.x = rr.x + gg.x * vv.x; vv.y = rr.y + gg.y * vv.y;
                        vv.z = rr.z + gg.z * vv.z; vv.w = rr.w + gg.w * vv.w;
                    } else if (EPI == 2) {
                        vv.x = gelu_f(vv.x); vv.y = gelu_f(vv.y);
                        vv.z = gelu_f(vv.z); vv.w = gelu_f(vv.w);
                    }
                    *(float4*)(crow + col) = vv;
                }
            }
        }
    }
    __syncthreads();
    if (tid < 32) tmem_dealloc(tmem, BN);
}

// ---------------- flash attention (unchanged) ----------------
__device__ __forceinline__ void ld_ktile(u32 dstb, const float* Kb, int jt, int tid) {
#pragma unroll
    for (int i = 0; i < 8; ++i) {
        int o = tid + (i << 8);
        int row = o >> 5, inner = o & 31, c = inner >> 3, s = inner & 7;
        cp16(dstb + c * 8192 + swz((u32)((row << 7) + (s << 4))),
             Kb + (size_t)(jt * 64 + row) * HD + (c << 5) + (s << 2));
    }
}
__device__ __forceinline__ void ld_vtile(u32 dstb, const float* Vb, int jt, int vLD, int tid) {
#pragma unroll
    for (int i = 0; i < 8; ++i) {
        int o = tid + (i << 8);
        int row = o >> 4, inner = o & 15, c = inner >> 3, s = inner & 7;
        cp16(dstb + c * 16384 + swz((u32)((row << 7) + (s << 4))),
             Vb + (size_t)row * vLD + jt * 64 + (c << 5) + (s << 2));
    }
}
#define IDESC_QK ((1u << 4) | (2u << 7) | (2u << 10) | (8u << 17) | (8u << 24))
#define IDESC_PV ((1u << 4) | (2u << 7) | (2u << 10) | (16u << 17) | (8u << 24))

__device__ __forceinline__ void issue_qk(u32 dcol, u32 sQ, u32 sKb) {
#pragma unroll
    for (int c = 0; c < 4; ++c) {
        u64 da = sdesc(sQ + c * 16384);
        u64 db = sdesc(sKb + c * 8192);
#pragma unroll
        for (int j = 0; j < 4; ++j)
            mma_tf32(dcol, da + j * 2, db + j * 2, IDESC_QK, (u32)((c | j) != 0));
    }
}
__device__ __forceinline__ void issue_pv(u32 dcol, u32 sPb, u32 sVb, bool first) {
#pragma unroll
    for (int c = 0; c < 2; ++c) {
        u64 da = sdesc(sPb + c * 16384);
        u64 db = sdesc(sVb + c * 16384);
#pragma unroll
        for (int j = 0; j < 4; ++j)
            mma_tf32(dcol, da + j * 2, db + j * 2, IDESC_PV,
                     (u32)(!(first && c == 0 && j == 0)));
    }
}

#define FL_SMEM (2048 + 65536 + 65536 + 65536 + 32768)

template <int SPLITOUT>
__global__ __launch_bounds__(256, 1)
void flash_kernel(const float* __restrict__ Qg, const float* __restrict__ Kg,
                  const float* __restrict__ Vg,
                  float* __restrict__ dst, float* __restrict__ lout,
                  size_t qHS, size_t kHS, size_t vHS, int vLD,
                  int nt, int nvalid, int ldd)
{
    extern __shared__ char smem[];
    float* rowsum = (float*)(smem + 16);
    const u32 sb = s2u(smem);
    const u32 mbar = sb + 8;
    const u32 sQ = sb + 2048;
    const u32 sK = sQ + 65536;
    const u32 sV = sK + 65536;
    const u32 sP = sV + 65536;

    const int h = blockIdx.y;
    const int tid = threadIdx.x;
    const int wid = tid >> 5, lane = tid & 31;
    const int hf = wid >> 2;
    const int r = ((wid & 3) << 5) + lane;
    const int t0 = SPLITOUT ? blockIdx.x * nt : 0;
    const int bm = SPLITOUT ? 0 : blockIdx.x * 128;

    const float* Qb = Qg + (size_t)h * qHS + (size_t)bm * HD;
    const float* Kb = Kg + (size_t)h * kHS;
    const float* Vb = Vg + (size_t)h * vHS;

#pragma unroll
    for (int i = 0; i < 16; ++i) {
        int o = tid + (i << 8);
        int row = o >> 5, inner = o & 31, c = inner >> 3, s = inner & 7;
        cp16(sQ + c * 16384 + swz((u32)((row << 7) + (s << 4))),
             Qb + (size_t)row * HD + (c << 5) + (s << 2));
    }
    ld_ktile(sK, Kb, t0, tid);
    ld_vtile(sV, Vb, t0, vLD, tid);
    cp_commit();
    if (nt > 1) ld_ktile(sK + 32768, Kb, t0 + 1, tid);
    cp_commit();

    if (tid == 0) mbar_init(mbar);
    if (tid < 32) { tmem_alloc(sb, 256); tmem_relinquish(); }
    __syncthreads();
    u32 tmem;
    asm volatile("ld.shared.b32 %0, [%1];" : "=r"(tmem) : "r"(sb));
    const u32 tO = tmem;

    cp_wait<1>();
    fence_async_shared();
    __syncthreads();
    if (tid < 32 && elect1()) {
        issue_qk(tmem + 128, sQ, sK);
        tc_commit(mbar);
    }

    float lacc = 0.f;
    u32 par = 0;

    for (int t = 0; t < nt; ++t) {
        const u32 scol = 128 + ((u32)(t & 1) << 6);

        mbar_wait(mbar, par); par ^= 1;
        tc_fence_after();
        cp_wait<0>();
        fence_async_shared();
        __syncthreads();

        if (tid < 32 && elect1()) {
            if (t + 1 < nt)
                issue_qk(tmem + 128 + ((u32)((t + 1) & 1) << 6),
                         sQ, sK + ((u32)((t + 1) & 1) * 32768u));
        }
        if (t + 2 < nt) ld_ktile(sK + ((u32)(t & 1) * 32768u), Kb, t0 + t + 2, tid);
        if (t + 1 < nt) ld_vtile(sV + ((u32)((t + 1) & 1) * 32768u), Vb, t0 + t + 1, vLD, tid);
        cp_commit();

        u32 sr[32];
        ldtm32(sr, tmem + scol + ((u32)hf << 5));
        tmem_wait_ld();
        float p[32];
        float ls = 0.f;
        const int jb = (t0 + t) * 64 + (hf << 5);
#pragma unroll
        for (int i = 0; i < 32; ++i) {
            float sv = __uint_as_float(sr[i]);
            float e = (jb + i < nvalid) ? __expf(sv) : 0.f;
            p[i] = e; ls += e;
        }
        lacc += ls;

        const u32 pbase = sP + (hf ? 16384u : 0u);
#pragma unroll
        for (int g = 0; g < 8; ++g) {
            u32 addr = pbase + swz(((u32)r << 7) + ((u32)g << 4));
            asm volatile("st.shared.v4.b32 [%0], {%1,%2,%3,%4};" :: "r"(addr),
                "r"(__float_as_uint(p[4 * g + 0])), "r"(__float_as_uint(p[4 * g + 1])),
                "r"(__float_as_uint(p[4 * g + 2])), "r"(__float_as_uint(p[4 * g + 3]))
                : "memory");
        }
        tc_fence_before();
        fence_async_shared();
        __syncthreads();

        if (tid < 32 && elect1()) {
            tc_fence_after();
            issue_pv(tO, sP, sV + ((u32)(t & 1) * 32768u), t == 0);
            tc_commit(mbar);
        }
    }

    mbar_wait(mbar, par);
    tc_fence_after();

    rowsum[r * 2 + hf] = lacc;
    __syncthreads();
    const float ltot = rowsum[r * 2] + rowsum[r * 2 + 1];

    if (SPLITOUT) {
        float* od = dst + (((size_t)blockIdx.x * NH + h) * 128 + r) * HD + (hf << 6);
#pragma unroll
        for (int g2 = 0; g2 < 2; ++g2) {
            u32 orgs[32];
            ldtm32(orgs, tO + ((u32)hf << 6) + ((u32)g2 << 5));
            tmem_wait_ld();
#pragma unroll
            for (int i = 0; i < 8; ++i) {
                float4 vv;
                vv.x = __uint_as_float(orgs[i * 4 + 0]);
                vv.y = __uint_as_float(orgs[i * 4 + 1]);
                vv.z = __uint_as_float(orgs[i * 4 + 2]);
                vv.w = __uint_as_float(orgs[i * 4 + 3]);
                *(float4*)(od + (g2 << 5) + i * 4) = vv;
            }
        }
        if (hf == 0)
            lout[((size_t)blockIdx.x * NH + h) * 128 + r] = ltot;
    } else {
        const float inv = 1.f / ltot;
        float* od = dst + (size_t)(bm + r) * ldd + h * HD + (hf << 6);
#pragma unroll
        for (int g2 = 0; g2 < 2; ++g2) {
            u32 orgs[32];
            ldtm32(orgs, tO + ((u32)hf << 6) + ((u32)g2 << 5));
            tmem_wait_ld();
#pragma unroll
            for (int i = 0; i < 8; ++i) {
                float4 vv;
                vv.x = __uint_as_float(orgs[i * 4 + 0]) * inv;
                vv.y = __uint_as_float(orgs[i * 4 + 1]) * inv;
                vv.z = __uint_as_float(orgs[i * 4 + 2]) * inv;
                vv.w = __uint_as_float(orgs[i * 4 + 3]) * inv;
                *(float4*)(od + (g2 << 5) + i * 4) = vv;
            }
        }
    }
    tc_fence_before();
    __syncthreads();
    if (tid < 32) tmem_dealloc(tmem, 256);
}

__global__ void combine2_kernel(const float* __restrict__ Op, const float* __restrict__ lp,
                                float* __restrict__ cat2)
{
    int r = blockIdx.x, h = blockIdx.y, d = threadIdx.x;
    float o = 0.f, l = 0.f;
#pragma unroll
    for (int s = 0; s < NSPLIT; ++s) {
        o += Op[(((size_t)s * NH + h) * 128 + r) * HD + d];
        l += lp[((size_t)s * NH + h) * 128 + r];
    }
    cat2[(size_t)r * CATW + h * HD + d] = o / l;
}

// ---------------- small elementwise kernels ----------------
__global__ void mod_kernel(const float* __restrict__ vec, const float* __restrict__ mw,
                           const float* __restrict__ mb, float* __restrict__ m)
{
    int o = blockIdx.x, t = threadIdx.x;
    float s = 0.f;
    for (int k = t; k < HID; k += 256) {
        float v = vec[k];
        s += (v / (1.f + expf(-v))) * mw[(size_t)o * HID + k];
    }
    __shared__ float red[256];
    red[t] = s; __syncthreads();
    for (int st = 128; st > 0; st >>= 1) { if (t < st) red[t] += red[t + st]; __syncthreads(); }
    if (t == 0) m[o] = red[0] + mb[o];
}

__global__ void ln_mod_kernel(const float* __restrict__ in, float* __restrict__ out,
                              const float* __restrict__ m)
{
    const int row = blockIdx.x, t = threadIdx.x;
    __shared__ float red[16];

    float4 xv = ((const float4*)(in + (size_t)row * HID))[t];

    float s = xv.x + xv.y + xv.z + xv.w;
#pragma unroll
    for (int o = 16; o; o >>= 1) s += __shfl_xor_sync(0xffffffffu, s, o);
    if ((t & 31) == 0) red[t >> 5] = s;
    __syncthreads();
    if (t < 32) {
        float v = (t < 12) ? red[t] : 0.f;
#pragma unroll
        for (int o = 8; o; o >>= 1) v += __shfl_xor_sync(0xffffffffu, v, o);
        if (t == 0) red[12] = v;
    }
    __syncthreads();
    const float mu = red[12] * (1.f / HID);
    __syncthreads();

    float4 d;
    d.x = xv.x - mu; d.y = xv.y - mu; d.z = xv.z - mu; d.w = xv.w - mu;
    float ss = d.x * d.x + d.y * d.y + d.z * d.z + d.w * d.w;
#pragma unroll
    for (int o = 16; o; o >>= 1) ss += __shfl_xor_sync(0xffffffffu, ss, o);
    if ((t & 31) == 0) red[t >> 5] = ss;
    __syncthreads();
    if (t < 32) {
        float v = (t < 12) ? red[t] : 0.f;
#pragma unroll
        for (int o = 8; o; o >>= 1) v += __shfl_xor_sync(0xffffffffu, v, o);
        if (t == 0) red[13] = v;
    }
    __syncthreads();
    const float inv = rsqrtf(red[13] * (1.f / HID) + 1e-6f);

    float4 sc = ((const float4*)(m + HID))[t];
    float4 sh = ((const float4*)m)[t];
    float4 ov;
    ov.x = (1.f + sc.x) * (d.x * inv) + sh.x;
    ov.y = (1.f + sc.y) * (d.y * inv) + sh.y;
    ov.z = (1.f + sc.z) * (d.z * inv) + sh.z;
    ov.w = (1.f + sc.w) * (d.w * inv) + sh.w;
    ((float4*)(out + (size_t)row * HID))[t] = ov;
}

__global__ void rmsrope_kernel(const float* __restrict__ src, int ldh,
                               const float* __restrict__ pe,
                               const float* __restrict__ scale,
                               float* __restrict__ dst, int dstL, float premul)
{
    int l = blockIdx.x, hd = blockIdx.y, d = threadIdx.x;
    float v = src[(size_t)l * ldh + hd * HD + d];
    __shared__ float sv[HD];
    __shared__ float wred[4];

    float ss = v * v;
#pragma unroll
    for (int o = 16; o > 0; o >>= 1) ss += __shfl_xor_sync(0xffffffffu, ss, o);
    if ((d & 31) == 0) wred[d >> 5] = ss;
    __syncthreads();
    float tot = wred[0] + wred[1] + wred[2] + wred[3];
    v = v * rsqrtf(tot * (1.f / HD) + 1e-6f) * scale[d] * premul;
    __syncthreads();

    sv[d] = v; __syncthreads();
    int i = d >> 1, j = d & 1;
    const float* pp = pe + (size_t)l * 256 + i * 4 + j * 2;
    float outv = pp[0] * sv[2 * i] + pp[1] * sv[2 * i + 1];

    dst[((size_t)hd * dstL + l) * HD + d] = outv;
}

__global__ void transpose_v(const float* __restrict__ src, int ldh,
                            float* __restrict__ dst, int dstL, int nrows)
{
    __shared__ float s[32][33];
    const int l0 = blockIdx.x * 32, d0 = blockIdx.y * 32, hd = blockIdx.z;
    const int tx = threadIdx.x, ty = threadIdx.y;
#pragma unroll
    for (int i = 0; i < 4; ++i) {
        int l = l0 + ty + i * 8;
        if (l < nrows)
            s[ty + i * 8][tx] = src[(size_t)l * ldh + hd * HD + d0 + tx];
    }
    __syncthreads();
#pragma unroll
    for (int i = 0; i < 4; ++i) {
        int d = d0 + ty + i * 8;
        int l = l0 + tx;
        if (l < nrows)
            dst[((size_t)hd * HD + d) * dstL + l] = s[tx][ty + i * 8];
    }
}

// ---------------- launch ----------------
#define SMEM_FOR(BN, S) (1024 + (S) * ((128 * 128) + (BN) * 128))

extern "C" void kernel_launch(void* const* d_in, const int* in_sizes, int n_in,
                              void* d_out, int out_size)
{
    (void)in_sizes; (void)n_in; (void)out_size;
    const float* x   = (const float*)d_in[0];
    const float* cps = (const float*)d_in[1];
    const float* vec = (const float*)d_in[2];
    const float* pe  = (const float*)d_in[3];
    const float* cpe = (const float*)d_in[4];
    const float* w1  = (const float*)d_in[5];
    const float* b1  = (const float*)d_in[6];
    const float* w2  = (const float*)d_in[7];
    const float* b2  = (const float*)d_in[8];
    const float* qs  = (const float*)d_in[9];
    const float* ks  = (const float*)d_in[10];
    const float* mw  = (const float*)d_in[11];
    const float* mb  = (const float*)d_in[12];
    float* out = (float*)d_out;

    const int SM256 = SMEM_FOR(256, 4);
    cudaFuncSetAttribute(tc_gemm<256, 4, 0>, cudaFuncAttributeMaxDynamicSharedMemorySize, SM256);
    cudaFuncSetAttribute(tc_gemm<256, 4, 1>, cudaFuncAttributeMaxDynamicSharedMemorySize, SM256);
    cudaFuncSetAttribute(tc_gemm<256, 4, 2>, cudaFuncAttributeMaxDynamicSharedMemorySize, SM256);
    cudaFuncSetAttribute(tc_cg2_merged, cudaFuncAttributeMaxDynamicSharedMemorySize, SMEM_CG);
    cudaFuncSetAttribute(tc_cg2_out, cudaFuncAttributeMaxDynamicSharedMemorySize, SMEM_CG);
    cudaFuncSetAttribute(flash_kernel<0>, cudaFuncAttributeMaxDynamicSharedMemorySize, FL_SMEM);
    cudaFuncSetAttribute(flash_kernel<1>, cudaFuncAttributeMaxDynamicSharedMemorySize, FL_SMEM);

    float *m, *xm, *xm2, *h, *h2kv, *h2f, *q, *k, *v, *q2, *k2, *v2, *cat, *cat2, *O2p, *l2;
    cudaGetSymbolAddress((void**)&m,    g_m);
    cudaGetSymbolAddress((void**)&xm,   g_xm);
    cudaGetSymbolAddress((void**)&xm2,  g_xm2);
    cudaGetSymbolAddress((void**)&h,    g_h);
    cudaGetSymbolAddress((void**)&h2kv, g_h2kv);
    cudaGetSymbolAddress((void**)&h2f,  g_h2f);
    cudaGetSymbolAddress((void**)&q,    g_q);
    cudaGetSymbolAddress((void**)&k,    g_k);
    cudaGetSymbolAddress((void**)&v,    g_v);
    cudaGetSymbolAddress((void**)&q2,   g_q2);
    cudaGetSymbolAddress((void**)&k2,   g_k2);
    cudaGetSymbolAddress((void**)&v2,   g_v2);
    cudaGetSymbolAddress((void**)&cat,  g_cat);
    cudaGetSymbolAddress((void**)&cat2, g_cat2);
    cudaGetSymbolAddress((void**)&O2p,  g_O2p);
    cudaGetSymbolAddress((void**)&l2,   g_l2);

    mod_kernel<<<3 * HID, 256>>>(vec, mw, mb, m);

    ln_mod_kernel<<<LX, 384>>>(x, xm, m);
    ln_mod_kernel<<<NC, 384>>>(cps, xm2, m);
    ln_mod_kernel<<<4096, 384>>>(x + (size_t)256 * HID, xm2 + (size_t)NC * HID, m);

    // merged cg2 GEMM: qkv -> h, mlp(gelu) -> cat[:,HID:], kv2 -> h2kv
    tc_cg2_merged<<<918, 256, SMEM_CG>>>(xm, xm2, w1, h, cat + HID, h2kv, b1);

    dim3 gqk(LX, NH);
    rmsrope_kernel<<<gqk, HD>>>(h + 0,   QKVW, pe, qs, q, LX, SOFT_SCALE);
    rmsrope_kernel<<<gqk, HD>>>(h + HID, QKVW, pe, ks, k, LX, 1.f);
    transpose_v<<<dim3(LX / 32, 4, NH), dim3(32, 8)>>>(h + 2 * HID, QKVW, v, LX, LX);

    dim3 gk2(L2V, NH);
    rmsrope_kernel<<<gk2, HD>>>(h2kv, 3072, cpe, ks, k2, L2P, 1.f);
    transpose_v<<<dim3((L2V + 31) / 32, 4, NH), dim3(32, 8)>>>(h2kv + HID, 3072, v2, L2P, L2V);

    tc_gemm<256, 4, 0><<<dim3(HID / 256, 1, 1), 256, SM256>>>(
        xm2, w1, h2f, HID, HID, HID, HID, 0, 0, 0, b1, nullptr, 0, nullptr, 128);
    tc_gemm<256, 4, 2><<<dim3(MLP / 256, 1, 1), 256, SM256>>>(
        xm2, w1 + (size_t)QKVW * HID, cat2 + HID, HID, HID, HID, CATW,
        0, 0, 0, b1 + QKVW, nullptr, 0, nullptr, 128);
    rmsrope_kernel<<<dim3(NC, NH), HD>>>(h2f, HID, cpe, qs, q2, 128, SOFT_SCALE);

    flash_kernel<0><<<dim3(LX / 128, NH), 256, FL_SMEM>>>(
        q, k, v, cat, nullptr,
        (size_t)LX * HD, (size_t)LX * HD, (size_t)HD * LX, LX,
        LX / 64, LX, CATW);

    // out_x = x + gate * (cat @ w2.T + b2)  (cg2, 51 tile-pairs)
    tc_cg2_out<<<102, 256, SMEM_CG>>>(cat, w2, out, b2, x, m + 2 * HID);

    flash_kernel<1><<<dim3(NSPLIT, NH), 256, FL_SMEM>>>(
        q2, k2, v2, O2p, l2,
        (size_t)128 * HD, (size_t)L2P * HD, (size_t)HD * L2P, L2P,
        L2P / 64 / NSPLIT, L2V, 0);
    combine2_kernel<<<dim3(NC, NH), HD>>>(O2p, l2, cat2);

    tc_gemm<256, 4, 1><<<dim3(HID / 256, 1, 1), 256, SM256>>>(
        cat2, w2, out + (size_t)LX * HID, CATW, CATW, CATW, HID,
        0, 0, 0, b2, cps, HID, m + 2 * HID, NC);
}